// round 2
// baseline (speedup 1.0000x reference)
#include <cuda_runtime.h>

// ---------------------------------------------------------------------------
// ConvTemporalGraphical
// K1: h0 partials = x[32,204800] @ W0[204800,256]  (K-split, smem-staged, f32x2)
// K2a: reduce 400 partials + b0 + ELU -> h0
// K2b: h1 = ELU(h0 @ W1 + b1)
// K3 : softmax(h1 @ W2 + b2) -> w[32,4]
// K4 : AS = sum_e w[n,e] A[e,t];  out[n,:,t,:] = x[n,:,t,:] @ AS
// ---------------------------------------------------------------------------

#define K_DIM 204800
#define M_DIM 32
#define N_DIM 256
#define SPLIT 400
#define KC    512   // K per block
#define KT    8     // K per smem tile
#define NTILES (KC / KT)

__device__ float g_partial[SPLIT * M_DIM * N_DIM];  // 13.1 MB scratch
__device__ float g_h0[M_DIM * N_DIM];
__device__ float g_h1[M_DIM * N_DIM];
__device__ float g_w[M_DIM * 4];

typedef unsigned long long u64;

__device__ __forceinline__ u64 pack2(float lo, float hi) {
    u64 r;
    asm("mov.b64 %0, {%1, %2};" : "=l"(r) : "f"(lo), "f"(hi));
    return r;
}
__device__ __forceinline__ void unpack2(u64 v, float& lo, float& hi) {
    asm("mov.b64 {%0, %1}, %2;" : "=f"(lo), "=f"(hi) : "l"(v));
}
__device__ __forceinline__ void ffma2(u64& d, u64 a, u64 b) {
    asm("fma.rn.f32x2 %0, %1, %2, %0;" : "+l"(d) : "l"(a), "l"(b));
}
__device__ __forceinline__ float elu(float v) {
    return v > 0.0f ? v : expm1f(v);
}

// ---------------------------------------------------------------------------
// K1: big GEMM. 128 threads, 4 blocks/SM. Tile M=32 x N=256 per block.
// Warp lane = mgrp(2b)*8 + ngrp(3b). Thread tile: 8 m x 8 n (4 f32x2 pairs).
// Bs: W0 tile [KT][256] (n-pairs read directly as u64).
// gs2: x tile duplicated [KT][64] so LDS.128 yields replicated f32x2 pairs.
// ---------------------------------------------------------------------------
__global__ __launch_bounds__(128, 4)
void gemm0_kernel(const float* __restrict__ x, const float* __restrict__ W0) {
    __shared__ __align__(16) float Bs[2][KT][256];
    __shared__ __align__(16) float gs2[2][KT][64];

    const int tid  = threadIdx.x;
    const int wid  = tid >> 5;
    const int lane = tid & 31;
    const int mgrp = lane >> 3;
    const int ngrp = lane & 7;
    const int n0   = wid * 64 + ngrp * 8;
    const int m0   = mgrp * 8;
    const long k0  = (long)blockIdx.x * KC;

    // load-thread mapping
    const int lkk = tid & 7;        // k within tile
    const int lmh = tid >> 3;       // 0..15 -> rows 2*lmh, 2*lmh+1

    u64 acc[8][4];
#pragma unroll
    for (int i = 0; i < 8; i++)
#pragma unroll
        for (int p = 0; p < 4; p++) acc[i][p] = 0ull;

    float4 breg[4];
    float  greg[2];

    // prologue: tile 0
    {
        const float4* src = (const float4*)(W0 + k0 * N_DIM);
#pragma unroll
        for (int j = 0; j < 4; j++) breg[j] = src[tid + j * 128];
#pragma unroll
        for (int r = 0; r < 2; r++)
            greg[r] = x[(long)(lmh * 2 + r) * K_DIM + k0 + lkk];
        float4* bd = (float4*)&Bs[0][0][0];
#pragma unroll
        for (int j = 0; j < 4; j++) bd[tid + j * 128] = breg[j];
#pragma unroll
        for (int r = 0; r < 2; r++)
            *(float2*)&gs2[0][lkk][2 * (lmh * 2 + r)] = make_float2(greg[r], greg[r]);
    }
    __syncthreads();

    int buf = 0;
    for (int t = 1; t < NTILES; ++t) {
        const long kt = k0 + (long)t * KT;
        // prefetch next tile into regs
        const float4* src = (const float4*)(W0 + kt * N_DIM);
#pragma unroll
        for (int j = 0; j < 4; j++) breg[j] = src[tid + j * 128];
#pragma unroll
        for (int r = 0; r < 2; r++)
            greg[r] = x[(long)(lmh * 2 + r) * K_DIM + kt + lkk];

        // compute current tile
        {
            const float (*Bb)[256] = Bs[buf];
            const float (*Gb)[64]  = gs2[buf];
#pragma unroll
            for (int kk = 0; kk < KT; ++kk) {
                const ulonglong2 wA = *(const ulonglong2*)&Bb[kk][n0];
                const ulonglong2 wB = *(const ulonglong2*)&Bb[kk][n0 + 4];
                const ulonglong2 gA = *(const ulonglong2*)&Gb[kk][2 * m0];
                const ulonglong2 gB = *(const ulonglong2*)&Gb[kk][2 * m0 + 4];
                const ulonglong2 gC = *(const ulonglong2*)&Gb[kk][2 * m0 + 8];
                const ulonglong2 gD = *(const ulonglong2*)&Gb[kk][2 * m0 + 12];
                const u64 gr[8] = {gA.x, gA.y, gB.x, gB.y, gC.x, gC.y, gD.x, gD.y};
#pragma unroll
                for (int i = 0; i < 8; i++) {
                    ffma2(acc[i][0], gr[i], wA.x);
                    ffma2(acc[i][1], gr[i], wA.y);
                    ffma2(acc[i][2], gr[i], wB.x);
                    ffma2(acc[i][3], gr[i], wB.y);
                }
            }
        }

        // store next tile
        {
            const int nb = buf ^ 1;
            float4* bd = (float4*)&Bs[nb][0][0];
#pragma unroll
            for (int j = 0; j < 4; j++) bd[tid + j * 128] = breg[j];
#pragma unroll
            for (int r = 0; r < 2; r++)
                *(float2*)&gs2[nb][lkk][2 * (lmh * 2 + r)] = make_float2(greg[r], greg[r]);
        }
        __syncthreads();
        buf ^= 1;
    }

    // last tile
    {
        const float (*Bb)[256] = Bs[buf];
        const float (*Gb)[64]  = gs2[buf];
#pragma unroll
        for (int kk = 0; kk < KT; ++kk) {
            const ulonglong2 wA = *(const ulonglong2*)&Bb[kk][n0];
            const ulonglong2 wB = *(const ulonglong2*)&Bb[kk][n0 + 4];
            const ulonglong2 gA = *(const ulonglong2*)&Gb[kk][2 * m0];
            const ulonglong2 gB = *(const ulonglong2*)&Gb[kk][2 * m0 + 4];
            const ulonglong2 gC = *(const ulonglong2*)&Gb[kk][2 * m0 + 8];
            const ulonglong2 gD = *(const ulonglong2*)&Gb[kk][2 * m0 + 12];
            const u64 gr[8] = {gA.x, gA.y, gB.x, gB.y, gC.x, gC.y, gD.x, gD.y};
#pragma unroll
            for (int i = 0; i < 8; i++) {
                ffma2(acc[i][0], gr[i], wA.x);
                ffma2(acc[i][1], gr[i], wA.y);
                ffma2(acc[i][2], gr[i], wB.x);
                ffma2(acc[i][3], gr[i], wB.y);
            }
        }
    }

    float* pout = g_partial + (long)blockIdx.x * (M_DIM * N_DIM);
#pragma unroll
    for (int i = 0; i < 8; i++) {
        float f[8];
#pragma unroll
        for (int p = 0; p < 4; p++) unpack2(acc[i][p], f[2 * p], f[2 * p + 1]);
        float* row = pout + (m0 + i) * N_DIM + n0;
        *(float4*)(row)     = make_float4(f[0], f[1], f[2], f[3]);
        *(float4*)(row + 4) = make_float4(f[4], f[5], f[6], f[7]);
    }
}

// ---------------------------------------------------------------------------
// K2a: reduce 400 partials (fixed order) + b0 + ELU. grid 256, block 256.
// block b: m = b>>3, n-chunk (b&7)*32. tid: n = chunk + (tid&31), slice tid>>5.
// ---------------------------------------------------------------------------
__global__ __launch_bounds__(256)
void reduce_kernel(const float* __restrict__ b0) {
    __shared__ float red[8][32];
    const int m  = blockIdx.x >> 3;
    const int nc = (blockIdx.x & 7) * 32;
    const int nl = threadIdx.x & 31;
    const int sl = threadIdx.x >> 5;
    const int n  = nc + nl;

    float s = 0.0f;
    const float* p = g_partial + (long)(sl * 50) * (M_DIM * N_DIM) + m * N_DIM + n;
#pragma unroll 10
    for (int i = 0; i < 50; i++) s += p[(long)i * (M_DIM * N_DIM)];
    red[sl][nl] = s;
    __syncthreads();
    if (sl == 0) {
        float a = b0[n];
#pragma unroll
        for (int j = 0; j < 8; j++) a += red[j][nl];
        g_h0[m * N_DIM + n] = elu(a);
    }
}

// ---------------------------------------------------------------------------
// K2b: h1 = ELU(h0 @ W1 + b1), one block per row m.
// ---------------------------------------------------------------------------
__global__ __launch_bounds__(256)
void mlp1_kernel(const float* __restrict__ W1, const float* __restrict__ b1) {
    __shared__ float hs[256];
    const int m = blockIdx.x;
    const int n = threadIdx.x;
    hs[n] = g_h0[m * N_DIM + n];
    __syncthreads();
    float a = b1[n];
#pragma unroll 8
    for (int k = 0; k < 256; k++) a += hs[k] * W1[k * 256 + n];
    g_h1[m * 256 + n] = elu(a);
}

// ---------------------------------------------------------------------------
// K3: logits = h1 @ W2 + b2, softmax over E=4.
// ---------------------------------------------------------------------------
__global__ void softmax_kernel(const float* __restrict__ W2,
                               const float* __restrict__ b2) {
    const int tid = threadIdx.x;   // 128 threads: (m, e)
    const int m = tid >> 2;
    const int e = tid & 3;
    float a = b2[e];
#pragma unroll 8
    for (int k = 0; k < 256; k++) a += g_h1[m * 256 + k] * W2[k * 4 + e];
    float mx = a;
    mx = fmaxf(mx, __shfl_xor_sync(0xffffffffu, mx, 1));
    mx = fmaxf(mx, __shfl_xor_sync(0xffffffffu, mx, 2));
    float ex = expf(a - mx);
    float sm = ex;
    sm += __shfl_xor_sync(0xffffffffu, sm, 1);
    sm += __shfl_xor_sync(0xffffffffu, sm, 2);
    g_w[m * 4 + e] = ex / sm;
}

// ---------------------------------------------------------------------------
// K4: block = (4 t's, one n). 256 thr = 4 groups x 64 c-threads.
// Thread holds acc[25] (as 12 f32x2 pairs + 1). AS padded to 26 for aligned
// LDS.64 pairs; AS reads are warp-broadcast, x reads conflict-free (25 ⊥ 32).
// ---------------------------------------------------------------------------
__global__ __launch_bounds__(256)
void gconv_kernel(const float* __restrict__ x, const float* __restrict__ A,
                  float* __restrict__ out) {
    __shared__ __align__(16) float ASs[4][25 * 26];   // [grp][v*26 + w]
    __shared__ float xs[4][64 * 25];                  // [grp][c*25 + v]
    const int tid = threadIdx.x;
    const int n   = blockIdx.y;
    const int t0  = blockIdx.x * 4;

    const float w0 = g_w[n * 4 + 0];
    const float w1 = g_w[n * 4 + 1];
    const float w2 = g_w[n * 4 + 2];
    const float w3 = g_w[n * 4 + 3];

    // mixed adjacency for the 4 t's of this block
    for (int idx = tid; idx < 4 * 625; idx += 256) {
        const int grp = idx / 625;
        const int j   = idx - grp * 625;
        const int v   = j / 25;
        const int w   = j - v * 25;
        const float* At = A + (long)(t0 + grp) * 625 + j;
        ASs[grp][v * 26 + w] = w0 * At[0]
                             + w1 * At[1 * 128 * 625]
                             + w2 * At[2 * 128 * 625]
                             + w3 * At[3 * 128 * 625];
    }
    // x tiles
    for (int idx = tid; idx < 4 * 1600; idx += 256) {
        const int grp = idx / 1600;
        const int r   = idx - grp * 1600;
        const int c   = r / 25;
        const int v   = r - c * 25;
        xs[grp][r] = x[(long)n * 204800 + (long)c * 3200 + (t0 + grp) * 25 + v];
    }
    __syncthreads();

    const int grp = tid >> 6;
    const int c   = tid & 63;
    const float* xr = &xs[grp][c * 25];
    const float* Ab = &ASs[grp][0];

    u64 acc2[12];
#pragma unroll
    for (int p = 0; p < 12; p++) acc2[p] = 0ull;
    float acc24 = 0.0f;

#pragma unroll
    for (int v = 0; v < 25; v++) {
        const float gv = xr[v];
        const u64 gr = pack2(gv, gv);
        const float* row = Ab + v * 26;
#pragma unroll
        for (int p = 0; p < 12; p++)
            ffma2(acc2[p], gr, *(const u64*)(row + 2 * p));
        acc24 += gv * row[24];
    }

    float* ob = out + (long)n * 204800 + (long)c * 3200 + (t0 + grp) * 25;
#pragma unroll
    for (int p = 0; p < 12; p++) {
        float lo, hi;
        unpack2(acc2[p], lo, hi);
        ob[2 * p]     = lo;
        ob[2 * p + 1] = hi;
    }
    ob[24] = acc24;
}

// ---------------------------------------------------------------------------
extern "C" void kernel_launch(void* const* d_in, const int* in_sizes, int n_in,
                              void* d_out, int out_size) {
    const float* x  = (const float*)d_in[0];
    const float* W0 = (const float*)d_in[1];
    const float* b0 = (const float*)d_in[2];
    const float* W1 = (const float*)d_in[3];
    const float* b1 = (const float*)d_in[4];
    const float* W2 = (const float*)d_in[5];
    const float* b2 = (const float*)d_in[6];
    const float* A  = (const float*)d_in[7];
    float* out = (float*)d_out;

    gemm0_kernel<<<SPLIT, 128>>>(x, W0);
    reduce_kernel<<<256, 256>>>(b0);
    mlp1_kernel<<<M_DIM, 256>>>(W1, b1);
    softmax_kernel<<<1, 128>>>(W2, b2);
    gconv_kernel<<<dim3(32, 32), 256>>>(x, A, out);
}

// round 3
// speedup vs baseline: 1.0299x; 1.0299x over previous
#include <cuda_runtime.h>

// ---------------------------------------------------------------------------
// ConvTemporalGraphical
// K1: partials = x[32,204800] @ W0[204800,256]  (K-split, smem double-buffer)
// K2: reduce 400 partials + b0 + ELU -> h0
// K3: gating: h1 = ELU(h0@W1+b1); softmax(h1@W2+b2) -> w[32,4]   (fused)
// K4: AS = sum_e w[n,e] A[e,t];  out[n,:,t,:] = x[n,:,t,:] @ AS
// ---------------------------------------------------------------------------

#define K_DIM 204800
#define M_DIM 32
#define N_DIM 256
#define SPLIT 400
#define KC    512   // K per block
#define KT    16    // K per smem tile
#define NTILES (KC / KT)

__device__ float g_partial[SPLIT * M_DIM * N_DIM];  // 13.1 MB scratch (L2-resident)
__device__ float g_h0[M_DIM * N_DIM];
__device__ float g_w[M_DIM * 4];

typedef unsigned long long u64;

__device__ __forceinline__ u64 pack2(float lo, float hi) {
    u64 r;
    asm("mov.b64 %0, {%1, %2};" : "=l"(r) : "f"(lo), "f"(hi));
    return r;
}
__device__ __forceinline__ void unpack2(u64 v, float& lo, float& hi) {
    asm("mov.b64 {%0, %1}, %2;" : "=f"(lo), "=f"(hi) : "l"(v));
}
__device__ __forceinline__ void ffma2(u64& d, u64 a, u64 b) {
    asm("fma.rn.f32x2 %0, %1, %2, %0;" : "+l"(d) : "l"(a), "l"(b));
}
__device__ __forceinline__ float elu(float v) {
    return v > 0.0f ? v : expm1f(v);
}

// ---------------------------------------------------------------------------
// K1: 256 threads, 3 blocks/SM (24 warps/SM for latency hiding).
// Block tile M=32 x N=256. Thread tile: 8 m x 4 n -> 16 u64 acc (n-pairs).
// Per k per thread: 1 LDS.128 (W pairs) + 4 LDS.128 (x replicated pairs,
// full warp broadcast) + 16 FFMA2. No pack MOVs in the hot loop.
// ---------------------------------------------------------------------------
__global__ __launch_bounds__(256, 3)
void gemm0_kernel(const float* __restrict__ x, const float* __restrict__ W0) {
    __shared__ __align__(16) float Bs[2][KT][256];   // W0 tile
    __shared__ __align__(16) float gs2[2][KT][64];   // x tile, duplicated

    const int tid  = threadIdx.x;
    const int ngrp = tid & 63;
    const int mgrp = tid >> 6;
    const int n0   = ngrp * 4;
    const int m0   = mgrp * 8;
    const long k0  = (long)blockIdx.x * KC;

    const int lkk = tid & 15;   // k within tile (loader)
    const int lmh = tid >> 4;   // 0..15 -> x rows lmh, lmh+16

    u64 acc[8][2];
#pragma unroll
    for (int i = 0; i < 8; i++) { acc[i][0] = 0ull; acc[i][1] = 0ull; }

    float4 breg[4];
    float  greg[2];

    // prologue: tile 0
    {
        const float4* src = (const float4*)(W0 + k0 * N_DIM);
#pragma unroll
        for (int j = 0; j < 4; j++) breg[j] = src[tid + j * 256];
        greg[0] = x[(long)lmh * K_DIM + k0 + lkk];
        greg[1] = x[(long)(lmh + 16) * K_DIM + k0 + lkk];
        float4* bd = (float4*)&Bs[0][0][0];
#pragma unroll
        for (int j = 0; j < 4; j++) bd[tid + j * 256] = breg[j];
        *(float2*)&gs2[0][lkk][2 * lmh]        = make_float2(greg[0], greg[0]);
        *(float2*)&gs2[0][lkk][2 * (lmh + 16)] = make_float2(greg[1], greg[1]);
    }
    __syncthreads();

    int buf = 0;
    for (int t = 1; t < NTILES; ++t) {
        const long kt = k0 + (long)t * KT;
        // prefetch next tile into registers
        const float4* src = (const float4*)(W0 + kt * N_DIM);
#pragma unroll
        for (int j = 0; j < 4; j++) breg[j] = src[tid + j * 256];
        greg[0] = x[(long)lmh * K_DIM + kt + lkk];
        greg[1] = x[(long)(lmh + 16) * K_DIM + kt + lkk];

        // compute current tile
        {
            const float (*Bb)[256] = Bs[buf];
            const float (*Gb)[64]  = gs2[buf];
#pragma unroll
            for (int kk = 0; kk < KT; ++kk) {
                const ulonglong2 w2 = *(const ulonglong2*)&Bb[kk][n0];
                const ulonglong2 gA = *(const ulonglong2*)&Gb[kk][2 * m0];
                const ulonglong2 gB = *(const ulonglong2*)&Gb[kk][2 * m0 + 4];
                const ulonglong2 gC = *(const ulonglong2*)&Gb[kk][2 * m0 + 8];
                const ulonglong2 gD = *(const ulonglong2*)&Gb[kk][2 * m0 + 12];
                const u64 gr[8] = {gA.x, gA.y, gB.x, gB.y, gC.x, gC.y, gD.x, gD.y};
#pragma unroll
                for (int i = 0; i < 8; i++) {
                    ffma2(acc[i][0], gr[i], w2.x);
                    ffma2(acc[i][1], gr[i], w2.y);
                }
            }
        }

        // store prefetched tile
        {
            const int nb = buf ^ 1;
            float4* bd = (float4*)&Bs[nb][0][0];
#pragma unroll
            for (int j = 0; j < 4; j++) bd[tid + j * 256] = breg[j];
            *(float2*)&gs2[nb][lkk][2 * lmh]        = make_float2(greg[0], greg[0]);
            *(float2*)&gs2[nb][lkk][2 * (lmh + 16)] = make_float2(greg[1], greg[1]);
        }
        __syncthreads();
        buf ^= 1;
    }

    // last tile
    {
        const float (*Bb)[256] = Bs[buf];
        const float (*Gb)[64]  = gs2[buf];
#pragma unroll
        for (int kk = 0; kk < KT; ++kk) {
            const ulonglong2 w2 = *(const ulonglong2*)&Bb[kk][n0];
            const ulonglong2 gA = *(const ulonglong2*)&Gb[kk][2 * m0];
            const ulonglong2 gB = *(const ulonglong2*)&Gb[kk][2 * m0 + 4];
            const ulonglong2 gC = *(const ulonglong2*)&Gb[kk][2 * m0 + 8];
            const ulonglong2 gD = *(const ulonglong2*)&Gb[kk][2 * m0 + 12];
            const u64 gr[8] = {gA.x, gA.y, gB.x, gB.y, gC.x, gC.y, gD.x, gD.y};
#pragma unroll
            for (int i = 0; i < 8; i++) {
                ffma2(acc[i][0], gr[i], w2.x);
                ffma2(acc[i][1], gr[i], w2.y);
            }
        }
    }

    float* pout = g_partial + (long)blockIdx.x * (M_DIM * N_DIM);
#pragma unroll
    for (int i = 0; i < 8; i++) {
        float f[4];
        unpack2(acc[i][0], f[0], f[1]);
        unpack2(acc[i][1], f[2], f[3]);
        *(float4*)(pout + (m0 + i) * N_DIM + n0) = make_float4(f[0], f[1], f[2], f[3]);
    }
}

// ---------------------------------------------------------------------------
// K2: reduce 400 partials (fixed order -> deterministic) + b0 + ELU.
// grid 256 blocks: block b -> m = b>>3, n-chunk = (b&7)*32.
// ---------------------------------------------------------------------------
__global__ __launch_bounds__(256)
void reduce_kernel(const float* __restrict__ b0) {
    __shared__ float red[8][32];
    const int m  = blockIdx.x >> 3;
    const int nc = (blockIdx.x & 7) * 32;
    const int nl = threadIdx.x & 31;
    const int sl = threadIdx.x >> 5;
    const int n  = nc + nl;

    float s = 0.0f;
    const float* p = g_partial + (long)(sl * 50) * (M_DIM * N_DIM) + m * N_DIM + n;
#pragma unroll 10
    for (int i = 0; i < 50; i++) s += p[(long)i * (M_DIM * N_DIM)];
    red[sl][nl] = s;
    __syncthreads();
    if (sl == 0) {
        float a = b0[n];
#pragma unroll
        for (int j = 0; j < 8; j++) a += red[j][nl];
        g_h0[m * N_DIM + n] = elu(a);
    }
}

// ---------------------------------------------------------------------------
// K3: fused gating. One block per row m (32 blocks, 256 threads).
//   h1 = ELU(h0 @ W1 + b1)  (thread n, coalesced W1 reads, unroll-8 MLP)
//   logits e = warp-reduced dot(h1, W2[:,e])   (warps 0..3)
//   softmax over 4 -> g_w[m]
// ---------------------------------------------------------------------------
__global__ __launch_bounds__(256)
void gating_kernel(const float* __restrict__ W1, const float* __restrict__ b1,
                   const float* __restrict__ W2, const float* __restrict__ b2) {
    __shared__ float hs[256];
    __shared__ float h1s[256];
    __shared__ float lg[4];
    const int m = blockIdx.x;
    const int n = threadIdx.x;

    hs[n] = g_h0[m * N_DIM + n];
    __syncthreads();

    float a = b1[n];
#pragma unroll 8
    for (int k = 0; k < 256; k++) a += hs[k] * W1[k * 256 + n];
    h1s[n] = elu(a);
    __syncthreads();

    const int w    = n >> 5;
    const int lane = n & 31;
    if (w < 4) {
        float s = 0.0f;
#pragma unroll
        for (int k = lane; k < 256; k += 32) s += h1s[k] * W2[k * 4 + w];
#pragma unroll
        for (int o = 16; o; o >>= 1) s += __shfl_xor_sync(0xffffffffu, s, o);
        if (lane == 0) lg[w] = s + b2[w];
    }
    __syncthreads();

    if (n < 4) {
        const float l0 = lg[0], l1 = lg[1], l2 = lg[2], l3 = lg[3];
        const float mx = fmaxf(fmaxf(l0, l1), fmaxf(l2, l3));
        const float e0 = expf(l0 - mx), e1 = expf(l1 - mx);
        const float e2 = expf(l2 - mx), e3 = expf(l3 - mx);
        const float inv = 1.0f / (e0 + e1 + e2 + e3);
        const float ev = (n == 0) ? e0 : (n == 1) ? e1 : (n == 2) ? e2 : e3;
        g_w[m * 4 + n] = ev * inv;
    }
}

// ---------------------------------------------------------------------------
// K4: block = (4 t's, one n). 256 thr = 4 groups x 64 c-threads.
// Thread holds acc[25] as 12 f32x2 pairs + 1. AS padded to 26 for aligned
// LDS.64 pairs; AS reads warp-broadcast, x reads conflict-free (25 coprime 32).
// ---------------------------------------------------------------------------
__global__ __launch_bounds__(256)
void gconv_kernel(const float* __restrict__ x, const float* __restrict__ A,
                  float* __restrict__ out) {
    __shared__ __align__(16) float ASs[4][25 * 26];   // [grp][v*26 + w]
    __shared__ float xs[4][64 * 25];                  // [grp][c*25 + v]
    const int tid = threadIdx.x;
    const int n   = blockIdx.y;
    const int t0  = blockIdx.x * 4;

    const float w0 = g_w[n * 4 + 0];
    const float w1 = g_w[n * 4 + 1];
    const float w2 = g_w[n * 4 + 2];
    const float w3 = g_w[n * 4 + 3];

    for (int idx = tid; idx < 4 * 625; idx += 256) {
        const int grp = idx / 625;
        const int j   = idx - grp * 625;
        const int v   = j / 25;
        const int w   = j - v * 25;
        const float* At = A + (long)(t0 + grp) * 625 + j;
        ASs[grp][v * 26 + w] = w0 * At[0]
                             + w1 * At[1 * 128 * 625]
                             + w2 * At[2 * 128 * 625]
                             + w3 * At[3 * 128 * 625];
    }
    for (int idx = tid; idx < 4 * 1600; idx += 256) {
        const int grp = idx / 1600;
        const int r   = idx - grp * 1600;
        const int c   = r / 25;
        const int v   = r - c * 25;
        xs[grp][r] = x[(long)n * 204800 + (long)c * 3200 + (t0 + grp) * 25 + v];
    }
    __syncthreads();

    const int grp = tid >> 6;
    const int c   = tid & 63;
    const float* xr = &xs[grp][c * 25];
    const float* Ab = &ASs[grp][0];

    u64 acc2[12];
#pragma unroll
    for (int p = 0; p < 12; p++) acc2[p] = 0ull;
    float acc24 = 0.0f;

#pragma unroll
    for (int v = 0; v < 25; v++) {
        const float gv = xr[v];
        const u64 gr = pack2(gv, gv);
        const float* row = Ab + v * 26;
#pragma unroll
        for (int p = 0; p < 12; p++)
            ffma2(acc2[p], gr, *(const u64*)(row + 2 * p));
        acc24 += gv * row[24];
    }

    float* ob = out + (long)n * 204800 + (long)c * 3200 + (t0 + grp) * 25;
#pragma unroll
    for (int p = 0; p < 12; p++) {
        float lo, hi;
        unpack2(acc2[p], lo, hi);
        ob[2 * p]     = lo;
        ob[2 * p + 1] = hi;
    }
    ob[24] = acc24;
}

// ---------------------------------------------------------------------------
extern "C" void kernel_launch(void* const* d_in, const int* in_sizes, int n_in,
                              void* d_out, int out_size) {
    const float* x  = (const float*)d_in[0];
    const float* W0 = (const float*)d_in[1];
    const float* b0 = (const float*)d_in[2];
    const float* W1 = (const float*)d_in[3];
    const float* b1 = (const float*)d_in[4];
    const float* W2 = (const float*)d_in[5];
    const float* b2 = (const float*)d_in[6];
    const float* A  = (const float*)d_in[7];
    float* out = (float*)d_out;

    gemm0_kernel<<<SPLIT, 256>>>(x, W0);
    reduce_kernel<<<256, 256>>>(b0);
    gating_kernel<<<M_DIM, 256>>>(W1, b1, W2, b2);
    gconv_kernel<<<dim3(32, 32), 256>>>(x, A, out);
}

// round 5
// speedup vs baseline: 1.3245x; 1.2861x over previous
#include <cuda_runtime.h>
#include <cuda_bf16.h>
#include <cstdint>

// ---------------------------------------------------------------------------
// ConvTemporalGraphical — warp-level mma.sync (bf16 split) edition.
// tcgen05 is unavailable: harness compiles PTX at .target sm_103 (no 'a').
// K1: partials = x[32,204800] @ W0[204800,256] via 3-term bf16 hi/lo mma.sync
// K2: reduce 256 partials + b0 + ELU -> h0
// K3: gating fused: h1=ELU(h0@W1+b1); softmax(h1@W2+b2) -> w[32,4]
// K4a: AS[n,t] = sum_e w[n,e] A[e,t]
// K4b: out[n,c,t,:] = x[n,c,t,:] @ AS[n,t]
// ---------------------------------------------------------------------------

#define K_DIM 204800
#define M_DIM 32
#define N_DIM 256
#define SPLIT 256
#define KC    800          // K per block
#define KSTEPS (KC / 16)   // 50

__device__ float g_partial[SPLIT * M_DIM * N_DIM];   // 8.4 MB
__device__ float g_h0[M_DIM * N_DIM];
__device__ float g_w[M_DIM * 4];
__device__ float g_AS[32 * 128 * 650];               // padded rows of 26

typedef unsigned long long u64;

__device__ __forceinline__ float elu(float v) { return v > 0.0f ? v : expm1f(v); }

__device__ __forceinline__ u64 pack2(float lo, float hi) {
    u64 r; asm("mov.b64 %0, {%1, %2};" : "=l"(r) : "f"(lo), "f"(hi)); return r;
}
__device__ __forceinline__ void unpack2(u64 v, float& lo, float& hi) {
    asm("mov.b64 {%0, %1}, %2;" : "=f"(lo), "=f"(hi) : "l"(v));
}
__device__ __forceinline__ void ffma2(u64& d, u64 a, u64 b) {
    asm("fma.rn.f32x2 %0, %1, %2, %0;" : "+l"(d) : "l"(a), "l"(b));
}

// split a float2 into bf16x2 hi and bf16x2 lo (residual)
__device__ __forceinline__ void split2(float a, float b, uint32_t& hi, uint32_t& lo) {
    __nv_bfloat162 h = __floats2bfloat162_rn(a, b);
    hi = *reinterpret_cast<uint32_t*>(&h);
    const float ra = a - __bfloat162float(h.x);
    const float rb = b - __bfloat162float(h.y);
    __nv_bfloat162 l = __floats2bfloat162_rn(ra, rb);
    lo = *reinterpret_cast<uint32_t*>(&l);
}

__device__ __forceinline__ void mma_bf16(float* d, const uint32_t* a,
                                         uint32_t b0, uint32_t b1) {
    asm volatile(
        "mma.sync.aligned.m16n8k16.row.col.f32.bf16.bf16.f32 "
        "{%0,%1,%2,%3}, {%4,%5,%6,%7}, {%8,%9}, {%0,%1,%2,%3};"
        : "+f"(d[0]), "+f"(d[1]), "+f"(d[2]), "+f"(d[3])
        : "r"(a[0]), "r"(a[1]), "r"(a[2]), "r"(a[3]), "r"(b0), "r"(b1));
}

// ---------------------------------------------------------------------------
// K1: block = K-chunk of 800 (50 k16-steps). 8 warps; warp w owns n-range
// [w*32, w*32+32) = 4 n-tiles of 8, and both m-tiles (M=32 = 2 x m16).
// A frags come straight from x as float2 (row-major match); B frags are
// scalar W0 loads (each element touched by exactly one lane chip-wide).
// 3 mma terms: Ah*Bh + Ah*Bl + Al*Bh  (fp32 accumulate).
// ---------------------------------------------------------------------------
__global__ __launch_bounds__(256, 2)
void gemm0_mma(const float* __restrict__ x, const float* __restrict__ W0) {
    const int tid  = threadIdx.x;
    const int w    = tid >> 5;
    const int lane = tid & 31;
    const int g    = lane >> 2;    // 0..7
    const int tg   = lane & 3;     // 0..3
    const int nbase = w * 32;

    float d[2][4][4];
#pragma unroll
    for (int mt = 0; mt < 2; mt++)
#pragma unroll
        for (int j = 0; j < 4; j++)
#pragma unroll
            for (int r = 0; r < 4; r++) d[mt][j][r] = 0.0f;

    int kk = blockIdx.x * KC;

#pragma unroll 2
    for (int ks = 0; ks < KSTEPS; ks++, kk += 16) {
        // ---- A fragments (hi/lo) for both m-tiles ----
        uint32_t ah[2][4], al[2][4];
#pragma unroll
        for (int mt = 0; mt < 2; mt++) {
            const int r0 = mt * 16 + g;
            const int r1 = r0 + 8;
            const float2 p0 = *(const float2*)(x + r0 * K_DIM + kk + 2 * tg);
            const float2 p1 = *(const float2*)(x + r1 * K_DIM + kk + 2 * tg);
            const float2 p2 = *(const float2*)(x + r0 * K_DIM + kk + 2 * tg + 8);
            const float2 p3 = *(const float2*)(x + r1 * K_DIM + kk + 2 * tg + 8);
            split2(p0.x, p0.y, ah[mt][0], al[mt][0]);
            split2(p1.x, p1.y, ah[mt][1], al[mt][1]);
            split2(p2.x, p2.y, ah[mt][2], al[mt][2]);
            split2(p3.x, p3.y, ah[mt][3], al[mt][3]);
        }

        // ---- B fragments per n-tile + 3-term MMAs ----
#pragma unroll
        for (int j = 0; j < 4; j++) {
            const int n = nbase + j * 8 + g;
            const float* bp = W0 + (kk + 2 * tg) * N_DIM + n;
            const float v0 = bp[0];
            const float v1 = bp[N_DIM];
            const float v2 = bp[8 * N_DIM];
            const float v3 = bp[9 * N_DIM];
            uint32_t bh0, bl0, bh1, bl1;
            split2(v0, v1, bh0, bl0);
            split2(v2, v3, bh1, bl1);
#pragma unroll
            for (int mt = 0; mt < 2; mt++) {
                mma_bf16(d[mt][j], ah[mt], bh0, bh1);
                mma_bf16(d[mt][j], ah[mt], bl0, bl1);
                mma_bf16(d[mt][j], al[mt], bh0, bh1);
            }
        }
    }

    // ---- store 32x256 partial tile ----
    float* po = g_partial + blockIdx.x * (M_DIM * N_DIM);
#pragma unroll
    for (int mt = 0; mt < 2; mt++) {
#pragma unroll
        for (int j = 0; j < 4; j++) {
            const int m0 = mt * 16 + g;
            const int n0 = nbase + j * 8 + 2 * tg;
            *(float2*)(po + m0 * N_DIM + n0)       = make_float2(d[mt][j][0], d[mt][j][1]);
            *(float2*)(po + (m0 + 8) * N_DIM + n0) = make_float2(d[mt][j][2], d[mt][j][3]);
        }
    }
}

// ---------------------------------------------------------------------------
// K2: reduce 256 partials (fixed order -> deterministic) + b0 + ELU.
// ---------------------------------------------------------------------------
__global__ __launch_bounds__(256)
void reduce_kernel(const float* __restrict__ b0) {
    __shared__ float red[8][32];
    const int m  = blockIdx.x >> 3;
    const int nc = (blockIdx.x & 7) * 32;
    const int nl = threadIdx.x & 31;
    const int sl = threadIdx.x >> 5;
    const int n  = nc + nl;

    float s = 0.0f;
    const float* p = g_partial + (sl * 32) * (M_DIM * N_DIM) + m * N_DIM + n;
#pragma unroll 8
    for (int i = 0; i < 32; i++) s += p[i * (M_DIM * N_DIM)];
    red[sl][nl] = s;
    __syncthreads();
    if (sl == 0) {
        float a = b0[n];
#pragma unroll
        for (int j = 0; j < 8; j++) a += red[j][nl];
        g_h0[m * N_DIM + n] = elu(a);
    }
}

// ---------------------------------------------------------------------------
// K3: fused gating (h1 MLP + logits + softmax), one block per row m.
// ---------------------------------------------------------------------------
__global__ __launch_bounds__(256)
void gating_kernel(const float* __restrict__ W1, const float* __restrict__ b1,
                   const float* __restrict__ W2, const float* __restrict__ b2) {
    __shared__ float hs[256];
    __shared__ float h1s[256];
    __shared__ float lg[4];
    const int m = blockIdx.x;
    const int n = threadIdx.x;

    hs[n] = g_h0[m * N_DIM + n];
    __syncthreads();

    float a = b1[n];
#pragma unroll 8
    for (int k = 0; k < 256; k++) a += hs[k] * W1[k * 256 + n];
    h1s[n] = elu(a);
    __syncthreads();

    const int w = n >> 5, lane = n & 31;
    if (w < 4) {
        float s = 0.0f;
#pragma unroll
        for (int k = lane; k < 256; k += 32) s += h1s[k] * W2[k * 4 + w];
#pragma unroll
        for (int o = 16; o; o >>= 1) s += __shfl_xor_sync(0xffffffffu, s, o);
        if (lane == 0) lg[w] = s + b2[w];
    }
    __syncthreads();

    if (n < 4) {
        const float l0 = lg[0], l1 = lg[1], l2 = lg[2], l3 = lg[3];
        const float mx = fmaxf(fmaxf(l0, l1), fmaxf(l2, l3));
        const float e0 = expf(l0 - mx), e1 = expf(l1 - mx);
        const float e2 = expf(l2 - mx), e3 = expf(l3 - mx);
        const float inv = 1.0f / (e0 + e1 + e2 + e3);
        const float ev = (n == 0) ? e0 : (n == 1) ? e1 : (n == 2) ? e2 : e3;
        g_w[m * 4 + n] = ev * inv;
    }
}

// ---------------------------------------------------------------------------
// K4a: AS[n,t] = sum_e w[n,e] A[e,t].  Block per t; A tile staged once.
// ---------------------------------------------------------------------------
__global__ __launch_bounds__(256)
void as_kernel(const float* __restrict__ A) {
    __shared__ float As[4][625];
    __shared__ float wn[128];
    const int t = blockIdx.x;
    const int tid = threadIdx.x;

    for (int i = tid; i < 4 * 625; i += 256) {
        const int e = i / 625;
        As[e][i - e * 625] = A[(e * 128 + t) * 625 + (i - e * 625)];
    }
    if (tid < 128) wn[tid] = g_w[tid];
    __syncthreads();

    for (int n = 0; n < 32; n++) {
        const float w0 = wn[n*4], w1 = wn[n*4+1], w2 = wn[n*4+2], w3 = wn[n*4+3];
        float* dst = g_AS + (n * 128 + t) * 650;
        for (int j = tid; j < 625; j += 256) {
            const int v = j / 25;
            dst[v * 26 + (j - v * 25)] =
                w0 * As[0][j] + w1 * As[1][j] + w2 * As[2][j] + w3 * As[3][j];
        }
    }
}

// ---------------------------------------------------------------------------
// K4b: block = (4 t's, n); 256 thr = 4 grp x 64 c. Coalesced xs fill
// (t-quad rows are 100 contiguous floats per c). acc as f32x2 pairs;
// AS reads warp-broadcast LDS.64, x reads conflict-free (25 coprime 32).
// ---------------------------------------------------------------------------
__global__ __launch_bounds__(256, 6)
void gconv_kernel(const float* __restrict__ x, float* __restrict__ out) {
    __shared__ __align__(16) float ASs[4][650];
    __shared__ float xs[4][64 * 25];
    const int tid = threadIdx.x;
    const int n   = blockIdx.y;
    const int t0  = blockIdx.x * 4;

    for (int i = tid; i < 4 * 650; i += 256)
        ASs[0][i] = g_AS[(n * 128 + t0) * 650 + i];

    const float* xb = x + n * K_DIM + t0 * 25;
    for (int idx = tid; idx < 6400; idx += 256) {
        const int c = idx / 100;
        const int j = idx - c * 100;          // j = grp*25 + v, contiguous in gmem
        const int grp = j / 25;
        const int v   = j - grp * 25;
        xs[grp][c * 25 + v] = xb[c * 3200 + j];
    }
    __syncthreads();

    const int grp = tid >> 6;
    const int c   = tid & 63;
    const float* xr = &xs[grp][c * 25];
    const float* Ab = &ASs[grp][0];

    u64 acc2[12];
#pragma unroll
    for (int p = 0; p < 12; p++) acc2[p] = 0ull;
    float acc24 = 0.0f;

#pragma unroll
    for (int v = 0; v < 25; v++) {
        const float gv = xr[v];
        const u64 gr = pack2(gv, gv);
        const float* row = Ab + v * 26;
#pragma unroll
        for (int p = 0; p < 12; p++) ffma2(acc2[p], gr, *(const u64*)(row + 2 * p));
        acc24 += gv * row[24];
    }

    float* ob = out + n * K_DIM + c * 3200 + (t0 + grp) * 25;
#pragma unroll
    for (int p = 0; p < 12; p++) {
        float lo, hi;
        unpack2(acc2[p], lo, hi);
        ob[2 * p] = lo; ob[2 * p + 1] = hi;
    }
    ob[24] = acc24;
}

// ---------------------------------------------------------------------------
extern "C" void kernel_launch(void* const* d_in, const int* in_sizes, int n_in,
                              void* d_out, int out_size) {
    const float* x  = (const float*)d_in[0];
    const float* W0 = (const float*)d_in[1];
    const float* b0 = (const float*)d_in[2];
    const float* W1 = (const float*)d_in[3];
    const float* b1 = (const float*)d_in[4];
    const float* W2 = (const float*)d_in[5];
    const float* b2 = (const float*)d_in[6];
    const float* A  = (const float*)d_in[7];
    float* out = (float*)d_out;

    gemm0_mma<<<SPLIT, 256>>>(x, W0);
    reduce_kernel<<<256, 256>>>(b0);
    gating_kernel<<<M_DIM, 256>>>(W1, b1, W2, b2);
    as_kernel<<<128, 256>>>(A);
    gconv_kernel<<<dim3(32, 32), 256>>>(x, out);
}

// round 6
// speedup vs baseline: 1.4719x; 1.1112x over previous
#include <cuda_runtime.h>
#include <cuda_bf16.h>
#include <cstdint>

// ---------------------------------------------------------------------------
// ConvTemporalGraphical — mma.sync bf16-split + coalesced-epilogue gconv.
// K1: partials = x[32,204800] @ W0[204800,256] via 3-term bf16 hi/lo mma.sync
// K2: reduce 256 partials + b0 + ELU -> h0
// K3: gating fused: h1=ELU(h0@W1+b1); softmax(h1@W2+b2) -> w[32,4]
// K4a: AS[n,t] = sum_e w[n,e] A[e,t]      (1024 blocks)
// K4b: out[n,c,t,:] = x[n,c,t,:] @ AS[n,t] (smem-staged coalesced I/O)
// ---------------------------------------------------------------------------

#define K_DIM 204800
#define M_DIM 32
#define N_DIM 256
#define SPLIT 256
#define KC    800          // K per block
#define KSTEPS (KC / 16)   // 50

__device__ float g_partial[SPLIT * M_DIM * N_DIM];   // 8.4 MB
__device__ float g_h0[M_DIM * N_DIM];
__device__ float g_w[M_DIM * 4];
__device__ float g_AS[32 * 128 * 650];               // padded rows of 26

typedef unsigned long long u64;

__device__ __forceinline__ float elu(float v) { return v > 0.0f ? v : expm1f(v); }

__device__ __forceinline__ u64 pack2(float lo, float hi) {
    u64 r; asm("mov.b64 %0, {%1, %2};" : "=l"(r) : "f"(lo), "f"(hi)); return r;
}
__device__ __forceinline__ void unpack2(u64 v, float& lo, float& hi) {
    asm("mov.b64 {%0, %1}, %2;" : "=f"(lo), "=f"(hi) : "l"(v));
}
__device__ __forceinline__ void ffma2(u64& d, u64 a, u64 b) {
    asm("fma.rn.f32x2 %0, %1, %2, %0;" : "+l"(d) : "l"(a), "l"(b));
}

// split a float2 into bf16x2 hi and bf16x2 lo (residual)
__device__ __forceinline__ void split2(float a, float b, uint32_t& hi, uint32_t& lo) {
    __nv_bfloat162 h = __floats2bfloat162_rn(a, b);
    hi = *reinterpret_cast<uint32_t*>(&h);
    const float ra = a - __bfloat162float(h.x);
    const float rb = b - __bfloat162float(h.y);
    __nv_bfloat162 l = __floats2bfloat162_rn(ra, rb);
    lo = *reinterpret_cast<uint32_t*>(&l);
}

__device__ __forceinline__ void mma_bf16(float* d, const uint32_t* a,
                                         uint32_t b0, uint32_t b1) {
    asm volatile(
        "mma.sync.aligned.m16n8k16.row.col.f32.bf16.bf16.f32 "
        "{%0,%1,%2,%3}, {%4,%5,%6,%7}, {%8,%9}, {%0,%1,%2,%3};"
        : "+f"(d[0]), "+f"(d[1]), "+f"(d[2]), "+f"(d[3])
        : "r"(a[0]), "r"(a[1]), "r"(a[2]), "r"(a[3]), "r"(b0), "r"(b1));
}

// ---------------------------------------------------------------------------
// K1: block = K-chunk of 800 (50 k16-steps). 8 warps; warp w owns n-range
// [w*32, w*32+32); A frags straight from x (float2); B frags scalar W0 loads
// (each W0 element touched by exactly one lane chip-wide -> 210MB stream).
// 3 mma terms: Ah*Bh + Ah*Bl + Al*Bh  (fp32 accumulate).
// ---------------------------------------------------------------------------
__global__ __launch_bounds__(256, 2)
void gemm0_mma(const float* __restrict__ x, const float* __restrict__ W0) {
    const int tid  = threadIdx.x;
    const int w    = tid >> 5;
    const int lane = tid & 31;
    const int g    = lane >> 2;    // 0..7
    const int tg   = lane & 3;     // 0..3
    const int nbase = w * 32;

    float d[2][4][4];
#pragma unroll
    for (int mt = 0; mt < 2; mt++)
#pragma unroll
        for (int j = 0; j < 4; j++)
#pragma unroll
            for (int r = 0; r < 4; r++) d[mt][j][r] = 0.0f;

    int kk = blockIdx.x * KC;

#pragma unroll 2
    for (int ks = 0; ks < KSTEPS; ks++, kk += 16) {
        uint32_t ah[2][4], al[2][4];
#pragma unroll
        for (int mt = 0; mt < 2; mt++) {
            const int r0 = mt * 16 + g;
            const int r1 = r0 + 8;
            const float2 p0 = *(const float2*)(x + r0 * K_DIM + kk + 2 * tg);
            const float2 p1 = *(const float2*)(x + r1 * K_DIM + kk + 2 * tg);
            const float2 p2 = *(const float2*)(x + r0 * K_DIM + kk + 2 * tg + 8);
            const float2 p3 = *(const float2*)(x + r1 * K_DIM + kk + 2 * tg + 8);
            split2(p0.x, p0.y, ah[mt][0], al[mt][0]);
            split2(p1.x, p1.y, ah[mt][1], al[mt][1]);
            split2(p2.x, p2.y, ah[mt][2], al[mt][2]);
            split2(p3.x, p3.y, ah[mt][3], al[mt][3]);
        }

#pragma unroll
        for (int j = 0; j < 4; j++) {
            const int n = nbase + j * 8 + g;
            const float* bp = W0 + (kk + 2 * tg) * N_DIM + n;
            const float v0 = bp[0];
            const float v1 = bp[N_DIM];
            const float v2 = bp[8 * N_DIM];
            const float v3 = bp[9 * N_DIM];
            uint32_t bh0, bl0, bh1, bl1;
            split2(v0, v1, bh0, bl0);
            split2(v2, v3, bh1, bl1);
#pragma unroll
            for (int mt = 0; mt < 2; mt++) {
                mma_bf16(d[mt][j], ah[mt], bh0, bh1);
                mma_bf16(d[mt][j], ah[mt], bl0, bl1);
                mma_bf16(d[mt][j], al[mt], bh0, bh1);
            }
        }
    }

    float* po = g_partial + blockIdx.x * (M_DIM * N_DIM);
#pragma unroll
    for (int mt = 0; mt < 2; mt++) {
#pragma unroll
        for (int j = 0; j < 4; j++) {
            const int m0 = mt * 16 + g;
            const int n0 = nbase + j * 8 + 2 * tg;
            *(float2*)(po + m0 * N_DIM + n0)       = make_float2(d[mt][j][0], d[mt][j][1]);
            *(float2*)(po + (m0 + 8) * N_DIM + n0) = make_float2(d[mt][j][2], d[mt][j][3]);
        }
    }
}

// ---------------------------------------------------------------------------
// K2: reduce 256 partials (fixed order -> deterministic) + b0 + ELU.
// ---------------------------------------------------------------------------
__global__ __launch_bounds__(256)
void reduce_kernel(const float* __restrict__ b0) {
    __shared__ float red[8][32];
    const int m  = blockIdx.x >> 3;
    const int nc = (blockIdx.x & 7) * 32;
    const int nl = threadIdx.x & 31;
    const int sl = threadIdx.x >> 5;
    const int n  = nc + nl;

    float s = 0.0f;
    const float* p = g_partial + (sl * 32) * (M_DIM * N_DIM) + m * N_DIM + n;
#pragma unroll 8
    for (int i = 0; i < 32; i++) s += p[i * (M_DIM * N_DIM)];
    red[sl][nl] = s;
    __syncthreads();
    if (sl == 0) {
        float a = b0[n];
#pragma unroll
        for (int j = 0; j < 8; j++) a += red[j][nl];
        g_h0[m * N_DIM + n] = elu(a);
    }
}

// ---------------------------------------------------------------------------
// K3: fused gating (h1 MLP + logits + softmax), one block per row m.
// ---------------------------------------------------------------------------
__global__ __launch_bounds__(256)
void gating_kernel(const float* __restrict__ W1, const float* __restrict__ b1,
                   const float* __restrict__ W2, const float* __restrict__ b2) {
    __shared__ float hs[256];
    __shared__ float h1s[256];
    __shared__ float lg[4];
    const int m = blockIdx.x;
    const int n = threadIdx.x;

    hs[n] = g_h0[m * N_DIM + n];
    __syncthreads();

    float a = b1[n];
#pragma unroll 8
    for (int k = 0; k < 256; k++) a += hs[k] * W1[k * 256 + n];
    h1s[n] = elu(a);
    __syncthreads();

    const int w = n >> 5, lane = n & 31;
    if (w < 4) {
        float s = 0.0f;
#pragma unroll
        for (int k = lane; k < 256; k += 32) s += h1s[k] * W2[k * 4 + w];
#pragma unroll
        for (int o = 16; o; o >>= 1) s += __shfl_xor_sync(0xffffffffu, s, o);
        if (lane == 0) lg[w] = s + b2[w];
    }
    __syncthreads();

    if (n < 4) {
        const float l0 = lg[0], l1 = lg[1], l2 = lg[2], l3 = lg[3];
        const float mx = fmaxf(fmaxf(l0, l1), fmaxf(l2, l3));
        const float e0 = expf(l0 - mx), e1 = expf(l1 - mx);
        const float e2 = expf(l2 - mx), e3 = expf(l3 - mx);
        const float inv = 1.0f / (e0 + e1 + e2 + e3);
        const float ev = (n == 0) ? e0 : (n == 1) ? e1 : (n == 2) ? e2 : e3;
        g_w[m * 4 + n] = ev * inv;
    }
}

// ---------------------------------------------------------------------------
// K4a: AS[n,t] = sum_e w[n,e] A[e,t].  Grid (128 t, 8 n-groups of 4).
// A tile staged once per block; writes padded rows of 26.
// ---------------------------------------------------------------------------
__global__ __launch_bounds__(256)
void as_kernel(const float* __restrict__ A) {
    __shared__ float As[4][625];
    const int t   = blockIdx.x;
    const int n0  = blockIdx.y * 4;
    const int tid = threadIdx.x;

    for (int i = tid; i < 4 * 625; i += 256) {
        const int e = i / 625;
        As[e][i - e * 625] = A[(e * 128 + t) * 625 + (i - e * 625)];
    }
    __syncthreads();

#pragma unroll
    for (int nn = 0; nn < 4; nn++) {
        const int n = n0 + nn;
        const float w0 = g_w[n * 4 + 0];
        const float w1 = g_w[n * 4 + 1];
        const float w2 = g_w[n * 4 + 2];
        const float w3 = g_w[n * 4 + 3];
        float* dst = g_AS + (n * 128 + t) * 650;
        for (int j = tid; j < 625; j += 256) {
            const int v = j / 25;
            dst[v * 26 + (j - v * 25)] =
                w0 * As[0][j] + w1 * As[1][j] + w2 * As[2][j] + w3 * As[3][j];
        }
    }
}

// ---------------------------------------------------------------------------
// K4b: block = (4 t's, n); 256 thr = 4 grp x 64 c.
// Phase 1: coalesced x stage into buf (xs layout).
// Phase 2: per-thread accumulate (AS broadcast LDS.64 + f32x2).
// Phase 3: sync, store results into buf as os[c][101-padded] (conflict-free),
//          then fully coalesced STG of 100-float runs.
// ---------------------------------------------------------------------------
__global__ __launch_bounds__(256, 4)
void gconv_kernel(const float* __restrict__ x, float* __restrict__ out) {
    __shared__ __align__(16) float ASs[4][650];   // 10.4 KB
    __shared__ float buf[64 * 101];               // 25.9 KB (xs then os)
    const int tid = threadIdx.x;
    const int n   = blockIdx.y;
    const int t0  = blockIdx.x * 4;

    for (int i = tid; i < 4 * 650; i += 256)
        ASs[0][i] = g_AS[(n * 128 + t0) * 650 + i];

    // xs stage: buf[grp*1600 + c*25 + v] <- x[n, c, t0+grp, v]  (coalesced)
    const float* xb = x + n * K_DIM + t0 * 25;
#pragma unroll
    for (int u = 0; u < 25; u++) {
        const int idx = u * 256 + tid;                 // 0..6399
        const int c = idx / 100;
        const int j = idx - c * 100;                   // grp*25 + v (contiguous)
        const int grp = j / 25;
        const int v   = j - grp * 25;
        buf[grp * 1600 + c * 25 + v] = xb[c * 3200 + j];
    }
    __syncthreads();

    const int grp = tid >> 6;
    const int c   = tid & 63;

    float rx[25];
    {
        const float* xr = &buf[grp * 1600 + c * 25];
#pragma unroll
        for (int v = 0; v < 25; v++) rx[v] = xr[v];
    }

    const float* Ab = &ASs[grp][0];
    u64 acc2[12];
#pragma unroll
    for (int p = 0; p < 12; p++) acc2[p] = 0ull;
    float acc24 = 0.0f;

#pragma unroll
    for (int v = 0; v < 25; v++) {
        const float gv = rx[v];
        const u64 gr = pack2(gv, gv);
        const float* row = Ab + v * 26;
#pragma unroll
        for (int p = 0; p < 12; p++) ffma2(acc2[p], gr, *(const u64*)(row + 2 * p));
        acc24 += gv * row[24];
    }

    __syncthreads();   // done reading xs; reuse buf as os

    // os[c][grp*25 + w], row pad 101 (stride 5 mod 32 -> conflict-free STS)
    {
        float* os = &buf[c * 101 + grp * 25];
#pragma unroll
        for (int p = 0; p < 12; p++) {
            float lo, hi;
            unpack2(acc2[p], lo, hi);
            os[2 * p] = lo; os[2 * p + 1] = hi;
        }
        os[24] = acc24;
    }
    __syncthreads();

    // coalesced output: out[n, c, t0*25 + j] <- os[c][j], j = 0..99
    float* ob = out + n * K_DIM + t0 * 25;
#pragma unroll
    for (int u = 0; u < 25; u++) {
        const int idx = u * 256 + tid;                 // 0..6399
        const int c2 = idx / 100;
        const int j  = idx - c2 * 100;
        ob[c2 * 3200 + j] = buf[c2 * 101 + j];
    }
}

// ---------------------------------------------------------------------------
extern "C" void kernel_launch(void* const* d_in, const int* in_sizes, int n_in,
                              void* d_out, int out_size) {
    const float* x  = (const float*)d_in[0];
    const float* W0 = (const float*)d_in[1];
    const float* b0 = (const float*)d_in[2];
    const float* W1 = (const float*)d_in[3];
    const float* b1 = (const float*)d_in[4];
    const float* W2 = (const float*)d_in[5];
    const float* b2 = (const float*)d_in[6];
    const float* A  = (const float*)d_in[7];
    float* out = (float*)d_out;

    gemm0_mma<<<SPLIT, 256>>>(x, W0);
    reduce_kernel<<<256, 256>>>(b0);
    gating_kernel<<<M_DIM, 256>>>(W1, b1, W2, b2);
    as_kernel<<<dim3(128, 8), 256>>>(A);
    gconv_kernel<<<dim3(32, 32), 256>>>(x, out);
}

// round 7
// speedup vs baseline: 1.6074x; 1.0921x over previous
#include <cuda_runtime.h>
#include <cuda_bf16.h>
#include <cstdint>

// ---------------------------------------------------------------------------
// ConvTemporalGraphical — mma.sync bf16-split, balanced single-wave GEMM,
// expert-mix fused into gconv (no AS intermediate).
// K1: partials = x[32,204800] @ W0[204800,256] via 3-term bf16 hi/lo mma.sync
// K2: reduce 296 partials + b0 + ELU -> h0
// K3: gating fused: h1=ELU(h0@W1+b1); softmax(h1@W2+b2) -> w[32,4]
// K4: gconv with in-block expert mix: AS = sum_e w[n,e] A[e,t] (smem),
//     out[n,c,t,:] = x[n,c,t,:] @ AS  (coalesced staged I/O)
// ---------------------------------------------------------------------------

#define K_DIM 204800
#define M_DIM 32
#define N_DIM 256
#define SPLIT 296              // = 2 * 148 SMs -> balanced single wave
#define KSTEPS_TOTAL 12800     // K / 16

__device__ float g_partial[SPLIT * M_DIM * N_DIM];   // 9.7 MB
__device__ float g_h0[M_DIM * N_DIM];
__device__ float g_w[M_DIM * 4];

typedef unsigned long long u64;

__device__ __forceinline__ float elu(float v) { return v > 0.0f ? v : expm1f(v); }

__device__ __forceinline__ u64 pack2(float lo, float hi) {
    u64 r; asm("mov.b64 %0, {%1, %2};" : "=l"(r) : "f"(lo), "f"(hi)); return r;
}
__device__ __forceinline__ void unpack2(u64 v, float& lo, float& hi) {
    asm("mov.b64 {%0, %1}, %2;" : "=f"(lo), "=f"(hi) : "l"(v));
}
__device__ __forceinline__ void ffma2(u64& d, u64 a, u64 b) {
    asm("fma.rn.f32x2 %0, %1, %2, %0;" : "+l"(d) : "l"(a), "l"(b));
}

// split a float2 into bf16x2 hi and bf16x2 lo (residual)
__device__ __forceinline__ void split2(float a, float b, uint32_t& hi, uint32_t& lo) {
    __nv_bfloat162 h = __floats2bfloat162_rn(a, b);
    hi = *reinterpret_cast<uint32_t*>(&h);
    const float ra = a - __bfloat162float(h.x);
    const float rb = b - __bfloat162float(h.y);
    __nv_bfloat162 l = __floats2bfloat162_rn(ra, rb);
    lo = *reinterpret_cast<uint32_t*>(&l);
}

__device__ __forceinline__ void mma_bf16(float* d, const uint32_t* a,
                                         uint32_t b0, uint32_t b1) {
    asm volatile(
        "mma.sync.aligned.m16n8k16.row.col.f32.bf16.bf16.f32 "
        "{%0,%1,%2,%3}, {%4,%5,%6,%7}, {%8,%9}, {%0,%1,%2,%3};"
        : "+f"(d[0]), "+f"(d[1]), "+f"(d[2]), "+f"(d[3])
        : "r"(a[0]), "r"(a[1]), "r"(a[2]), "r"(a[3]), "r"(b0), "r"(b1));
}

// ---------------------------------------------------------------------------
// K1: block = variable K-chunk (43-44 k16-steps, balanced over 296 blocks).
// 8 warps; warp w owns n-range [w*32, w*32+32); A frags straight from x
// (float2); B frags scalar W0 loads (each W0 element read by exactly one
// lane chip-wide -> one clean 210MB stream).
// 3 mma terms: Ah*Bh + Ah*Bl + Al*Bh  (fp32 accumulate).
// ---------------------------------------------------------------------------
__global__ __launch_bounds__(256, 2)
void gemm0_mma(const float* __restrict__ x, const float* __restrict__ W0) {
    const int tid  = threadIdx.x;
    const int w    = tid >> 5;
    const int lane = tid & 31;
    const int g    = lane >> 2;    // 0..7
    const int tg   = lane & 3;     // 0..3
    const int nbase = w * 32;

    const int ks_beg = (int)(((long)blockIdx.x       * KSTEPS_TOTAL) / SPLIT);
    const int ks_end = (int)(((long)(blockIdx.x + 1) * KSTEPS_TOTAL) / SPLIT);

    float d[2][4][4];
#pragma unroll
    for (int mt = 0; mt < 2; mt++)
#pragma unroll
        for (int j = 0; j < 4; j++)
#pragma unroll
            for (int r = 0; r < 4; r++) d[mt][j][r] = 0.0f;

#pragma unroll 2
    for (int ks = ks_beg; ks < ks_end; ks++) {
        const int kk = ks * 16;
        uint32_t ah[2][4], al[2][4];
#pragma unroll
        for (int mt = 0; mt < 2; mt++) {
            const int r0 = mt * 16 + g;
            const int r1 = r0 + 8;
            const float2 p0 = *(const float2*)(x + r0 * K_DIM + kk + 2 * tg);
            const float2 p1 = *(const float2*)(x + r1 * K_DIM + kk + 2 * tg);
            const float2 p2 = *(const float2*)(x + r0 * K_DIM + kk + 2 * tg + 8);
            const float2 p3 = *(const float2*)(x + r1 * K_DIM + kk + 2 * tg + 8);
            split2(p0.x, p0.y, ah[mt][0], al[mt][0]);
            split2(p1.x, p1.y, ah[mt][1], al[mt][1]);
            split2(p2.x, p2.y, ah[mt][2], al[mt][2]);
            split2(p3.x, p3.y, ah[mt][3], al[mt][3]);
        }

#pragma unroll
        for (int j = 0; j < 4; j++) {
            const int n = nbase + j * 8 + g;
            const float* bp = W0 + (kk + 2 * tg) * N_DIM + n;
            const float v0 = bp[0];
            const float v1 = bp[N_DIM];
            const float v2 = bp[8 * N_DIM];
            const float v3 = bp[9 * N_DIM];
            uint32_t bh0, bl0, bh1, bl1;
            split2(v0, v1, bh0, bl0);
            split2(v2, v3, bh1, bl1);
#pragma unroll
            for (int mt = 0; mt < 2; mt++) {
                mma_bf16(d[mt][j], ah[mt], bh0, bh1);
                mma_bf16(d[mt][j], ah[mt], bl0, bl1);
                mma_bf16(d[mt][j], al[mt], bh0, bh1);
            }
        }
    }

    float* po = g_partial + blockIdx.x * (M_DIM * N_DIM);
#pragma unroll
    for (int mt = 0; mt < 2; mt++) {
#pragma unroll
        for (int j = 0; j < 4; j++) {
            const int m0 = mt * 16 + g;
            const int n0 = nbase + j * 8 + 2 * tg;
            *(float2*)(po + m0 * N_DIM + n0)       = make_float2(d[mt][j][0], d[mt][j][1]);
            *(float2*)(po + (m0 + 8) * N_DIM + n0) = make_float2(d[mt][j][2], d[mt][j][3]);
        }
    }
}

// ---------------------------------------------------------------------------
// K2: reduce 296 partials (fixed order -> deterministic) + b0 + ELU.
// grid 256: block b -> m = b>>3, n-chunk = (b&7)*32. 8 warps x 37 slices.
// ---------------------------------------------------------------------------
__global__ __launch_bounds__(256)
void reduce_kernel(const float* __restrict__ b0) {
    __shared__ float red[8][32];
    const int m  = blockIdx.x >> 3;
    const int nc = (blockIdx.x & 7) * 32;
    const int nl = threadIdx.x & 31;
    const int sl = threadIdx.x >> 5;
    const int n  = nc + nl;

    float s = 0.0f;
    const float* p = g_partial + (sl * 37) * (M_DIM * N_DIM) + m * N_DIM + n;
#pragma unroll
    for (int i = 0; i < 37; i++) s += p[i * (M_DIM * N_DIM)];
    red[sl][nl] = s;
    __syncthreads();
    if (sl == 0) {
        float a = b0[n];
#pragma unroll
        for (int j = 0; j < 8; j++) a += red[j][nl];
        g_h0[m * N_DIM + n] = elu(a);
    }
}

// ---------------------------------------------------------------------------
// K3: fused gating (h1 MLP + logits + softmax), one block per row m.
// ---------------------------------------------------------------------------
__global__ __launch_bounds__(256)
void gating_kernel(const float* __restrict__ W1, const float* __restrict__ b1,
                   const float* __restrict__ W2, const float* __restrict__ b2) {
    __shared__ float hs[256];
    __shared__ float h1s[256];
    __shared__ float lg[4];
    const int m = blockIdx.x;
    const int n = threadIdx.x;

    hs[n] = g_h0[m * N_DIM + n];
    __syncthreads();

    float a = b1[n];
#pragma unroll 8
    for (int k = 0; k < 256; k++) a += hs[k] * W1[k * 256 + n];
    h1s[n] = elu(a);
    __syncthreads();

    const int w = n >> 5, lane = n & 31;
    if (w < 4) {
        float s = 0.0f;
#pragma unroll
        for (int k = lane; k < 256; k += 32) s += h1s[k] * W2[k * 4 + w];
#pragma unroll
        for (int o = 16; o; o >>= 1) s += __shfl_xor_sync(0xffffffffu, s, o);
        if (lane == 0) lg[w] = s + b2[w];
    }
    __syncthreads();

    if (n < 4) {
        const float l0 = lg[0], l1 = lg[1], l2 = lg[2], l3 = lg[3];
        const float mx = fmaxf(fmaxf(l0, l1), fmaxf(l2, l3));
        const float e0 = expf(l0 - mx), e1 = expf(l1 - mx);
        const float e2 = expf(l2 - mx), e3 = expf(l3 - mx);
        const float inv = 1.0f / (e0 + e1 + e2 + e3);
        const float ev = (n == 0) ? e0 : (n == 1) ? e1 : (n == 2) ? e2 : e3;
        g_w[m * 4 + n] = ev * inv;
    }
}

// ---------------------------------------------------------------------------
// K4: block = (4 t's, n); 256 thr = 4 grp x 64 c.
// Phase 0: expert mix in-block: ASs[grp] = sum_e w[n,e] A[e, t0+grp] (A L2-hot)
// Phase 1: coalesced x stage into buf.
// Phase 2: per-thread accumulate (AS broadcast LDS.64 + f32x2).
// Phase 3: stage results os[c][101-pad] then fully coalesced STG.
// ---------------------------------------------------------------------------
__global__ __launch_bounds__(256, 4)
void gconv_kernel(const float* __restrict__ x, const float* __restrict__ A,
                  float* __restrict__ out) {
    __shared__ __align__(16) float ASs[4][650];   // 10.4 KB
    __shared__ float buf[64 * 101];               // 25.9 KB (xs then os)
    const int tid = threadIdx.x;
    const int n   = blockIdx.y;
    const int t0  = blockIdx.x * 4;

    const float w0 = g_w[n * 4 + 0];
    const float w1 = g_w[n * 4 + 1];
    const float w2 = g_w[n * 4 + 2];
    const float w3 = g_w[n * 4 + 3];

    // Phase 0: mixed adjacency (A[e,t,v,w] at (e*128 + t)*625)
    for (int idx = tid; idx < 2500; idx += 256) {
        const int grp = idx / 625;
        const int j   = idx - grp * 625;
        const int v   = j / 25;
        const int ww  = j - v * 25;
        const float* At = A + (t0 + grp) * 625 + j;
        ASs[grp][v * 26 + ww] = w0 * At[0]
                              + w1 * At[1 * 128 * 625]
                              + w2 * At[2 * 128 * 625]
                              + w3 * At[3 * 128 * 625];
    }

    // Phase 1: xs stage (coalesced 100-float runs per c)
    const float* xb = x + n * K_DIM + t0 * 25;
#pragma unroll
    for (int u = 0; u < 25; u++) {
        const int idx = u * 256 + tid;                 // 0..6399
        const int c = idx / 100;
        const int j = idx - c * 100;                   // grp*25 + v (contiguous)
        const int grp = j / 25;
        const int v   = j - grp * 25;
        buf[grp * 1600 + c * 25 + v] = xb[c * 3200 + j];
    }
    __syncthreads();

    const int grp = tid >> 6;
    const int c   = tid & 63;

    float rx[25];
    {
        const float* xr = &buf[grp * 1600 + c * 25];
#pragma unroll
        for (int v = 0; v < 25; v++) rx[v] = xr[v];
    }

    const float* Ab = &ASs[grp][0];
    u64 acc2[12];
#pragma unroll
    for (int p = 0; p < 12; p++) acc2[p] = 0ull;
    float acc24 = 0.0f;

#pragma unroll
    for (int v = 0; v < 25; v++) {
        const float gv = rx[v];
        const u64 gr = pack2(gv, gv);
        const float* row = Ab + v * 26;
#pragma unroll
        for (int p = 0; p < 12; p++) ffma2(acc2[p], gr, *(const u64*)(row + 2 * p));
        acc24 += gv * row[24];
    }

    __syncthreads();   // done reading xs; reuse buf as os

    {
        float* os = &buf[c * 101 + grp * 25];
#pragma unroll
        for (int p = 0; p < 12; p++) {
            float lo, hi;
            unpack2(acc2[p], lo, hi);
            os[2 * p] = lo; os[2 * p + 1] = hi;
        }
        os[24] = acc24;
    }
    __syncthreads();

    // Phase 3: coalesced output
    float* ob = out + n * K_DIM + t0 * 25;
#pragma unroll
    for (int u = 0; u < 25; u++) {
        const int idx = u * 256 + tid;
        const int c2 = idx / 100;
        const int j  = idx - c2 * 100;
        ob[c2 * 3200 + j] = buf[c2 * 101 + j];
    }
}

// ---------------------------------------------------------------------------
extern "C" void kernel_launch(void* const* d_in, const int* in_sizes, int n_in,
                              void* d_out, int out_size) {
    const float* x  = (const float*)d_in[0];
    const float* W0 = (const float*)d_in[1];
    const float* b0 = (const float*)d_in[2];
    const float* W1 = (const float*)d_in[3];
    const float* b1 = (const float*)d_in[4];
    const float* W2 = (const float*)d_in[5];
    const float* b2 = (const float*)d_in[6];
    const float* A  = (const float*)d_in[7];
    float* out = (float*)d_out;

    gemm0_mma<<<SPLIT, 256>>>(x, W0);
    reduce_kernel<<<256, 256>>>(b0);
    gating_kernel<<<M_DIM, 256>>>(W1, b1, W2, b2);
    gconv_kernel<<<dim3(32, 32), 256>>>(x, A, out);
}